// round 15
// baseline (speedup 1.0000x reference)
#include <cuda_runtime.h>
#include <cstdint>
#include <math.h>

#define BATCHN 4
#define SEQ    1024
#define DMODEL 4096
#define NHEAD  32
#define HDIM   128
#define TOKENS 4096
#define MAX_POS 10000

// ---------------- scratch (device globals; malloc banned) ------------------
__device__ float g_xr [(size_t)TOKENS * DMODEL];
__device__ float g_wqr[(size_t)DMODEL * DMODEL];
__device__ float g_wkr[(size_t)DMODEL * DMODEL];
__device__ float g_wvr[(size_t)DMODEL * DMODEL];
__device__ float g_wor[(size_t)DMODEL * DMODEL];
__device__ float g_qr [(size_t)TOKENS * DMODEL];
__device__ float g_kr [(size_t)TOKENS * DMODEL];
__device__ float g_vt [(size_t)BATCHN * NHEAD * HDIM * SEQ];
__device__ float g_cos[SEQ * 16];
__device__ float g_sin[SEQ * 16];

// ---------------- helpers ---------------------------------------------------
__device__ __forceinline__ uint32_t su32(const void* p) {
    return (uint32_t)__cvta_generic_to_shared(p);
}
__device__ __forceinline__ float tf32r(float x) {
    uint32_t u;
    asm("cvt.rna.tf32.f32 %0, %1;" : "=r"(u) : "f"(x));
    return __uint_as_float(u);
}
__device__ __forceinline__ int permc(int k) {
    int kk = k & 15;
    return (k & ~15) | ((kk & 3) << 2) | (kk >> 2);
}
__device__ __forceinline__ void cpa(uint32_t s, const void* g) {
    asm volatile("cp.async.cg.shared.global [%0], [%1], 16;" :: "r"(s), "l"(g));
}
__device__ __forceinline__ void cpa_commit() {
    asm volatile("cp.async.commit_group;" ::: "memory");
}
template <int N> __device__ __forceinline__ void cpa_wait() {
    asm volatile("cp.async.wait_group %0;" :: "n"(N) : "memory");
}
__device__ __forceinline__ void lds4(uint32_t* v, uint32_t a) {
    asm volatile("ld.shared.v4.b32 {%0,%1,%2,%3}, [%4];"
                 : "=r"(v[0]), "=r"(v[1]), "=r"(v[2]), "=r"(v[3]) : "r"(a));
}
__device__ __forceinline__ void mma8(float* c, uint32_t a0, uint32_t a1, uint32_t a2,
                                     uint32_t a3, uint32_t b0, uint32_t b1) {
    asm volatile(
        "mma.sync.aligned.m16n8k8.row.col.f32.tf32.tf32.f32 "
        "{%0,%1,%2,%3},{%4,%5,%6,%7},{%8,%9},{%0,%1,%2,%3};"
        : "+f"(c[0]), "+f"(c[1]), "+f"(c[2]), "+f"(c[3])
        : "r"(a0), "r"(a1), "r"(a2), "r"(a3), "r"(b0), "r"(b1));
}

// 128x128x32 warp-tile mma core (8 warps 2x4, warp 64x32) — used by flash
__device__ __forceinline__ void mma_core(uint32_t ab, uint32_t bb,
                                         float acc[4][4][4], int wm, int wn, int l) {
#pragma unroll
    for (int g = 0; g < 2; g++) {
        uint32_t bfr[4][4];
#pragma unroll
        for (int nt = 0; nt < 4; nt++) {
            int r = wn * 32 + nt * 8 + (l >> 2);
            lds4(bfr[nt], bb + r * 128 + (((g * 4 + (l & 3)) ^ ((r & 1) << 2)) << 4));
        }
#pragma unroll
        for (int mt = 0; mt < 4; mt++) {
            int r0 = wm * 64 + mt * 16 + (l >> 2), r1 = r0 + 8;
            uint32_t a0[4], a1[4];
            lds4(a0, ab + r0 * 128 + (((g * 4 + (l & 3)) ^ ((r0 & 1) << 2)) << 4));
            lds4(a1, ab + r1 * 128 + (((g * 4 + (l & 3)) ^ ((r1 & 1) << 2)) << 4));
#pragma unroll
            for (int nt = 0; nt < 4; nt++)
                mma8(acc[mt][nt], a0[0], a1[0], a0[1], a1[1], bfr[nt][0], bfr[nt][1]);
#pragma unroll
            for (int nt = 0; nt < 4; nt++)
                mma8(acc[mt][nt], a0[2], a1[2], a0[3], a1[3], bfr[nt][2], bfr[nt][3]);
        }
    }
}

// 128x128x32 with 4 warps (2x2) of 64x64: halves smem re-reads per MAC
__device__ __forceinline__ void mma_core44(uint32_t ab, uint32_t bb,
                                           float acc[4][8][4], int wm, int wn, int l) {
#pragma unroll
    for (int g = 0; g < 2; g++) {
        uint32_t bfr[8][4];
#pragma unroll
        for (int nt = 0; nt < 8; nt++) {
            int r = wn * 64 + nt * 8 + (l >> 2);
            lds4(bfr[nt], bb + r * 128 + (((g * 4 + (l & 3)) ^ ((r & 1) << 2)) << 4));
        }
#pragma unroll
        for (int mt = 0; mt < 4; mt++) {
            int r0 = wm * 64 + mt * 16 + (l >> 2), r1 = r0 + 8;
            uint32_t a0[4], a1[4];
            lds4(a0, ab + r0 * 128 + (((g * 4 + (l & 3)) ^ ((r0 & 1) << 2)) << 4));
            lds4(a1, ab + r1 * 128 + (((g * 4 + (l & 3)) ^ ((r1 & 1) << 2)) << 4));
#pragma unroll
            for (int nt = 0; nt < 8; nt++)
                mma8(acc[mt][nt], a0[0], a1[0], a0[1], a1[1], bfr[nt][0], bfr[nt][1]);
#pragma unroll
            for (int nt = 0; nt < 8; nt++)
                mma8(acc[mt][nt], a0[2], a1[2], a0[3], a1[3], bfr[nt][2], bfr[nt][3]);
        }
    }
}

constexpr int STAGES = 3;
constexpr int SMEM_GEMM = STAGES * 32768;   // 96KB

__device__ __forceinline__ void raster(int pid, int& m0, int& n0) {
    const int gs = 8 * 32;
    int gid = pid / gs, r = pid - gid * gs;
    m0 = (gid * 8 + (r & 7)) * 128;
    n0 = (r >> 3) * 128;
}

// 4-warp (128-thread) GEMM mainloop: 128x128 tile, K=4096
__device__ __forceinline__ void gemm_main4(
    const float* A, const float* B,
    uint32_t sb, float acc[4][8][4], int tid, int wm, int wn, int l)
{
    const int nK = DMODEL / 32;
    auto fill = [&](int kt, int s) {
        const uint32_t ab = sb + s * 32768;
        const float* ag = A + kt * 32;
        const float* bg = B + kt * 32;
#pragma unroll
        for (int i = 0; i < 8; i++) {
            int ch = tid + i * 128, r = ch >> 3, c = ch & 7;
            cpa(ab + r * 128 + ((c ^ ((r & 1) << 2)) << 4),
                ag + (long long)r * DMODEL + c * 4);
        }
#pragma unroll
        for (int i = 0; i < 8; i++) {
            int ch = tid + i * 128, r = ch >> 3, c = ch & 7;
            cpa(ab + 16384 + r * 128 + ((c ^ ((r & 1) << 2)) << 4),
                bg + (long long)r * DMODEL + c * 4);
        }
        cpa_commit();
    };
    for (int s = 0; s < STAGES - 1; s++) fill(s, s);
    for (int kt = 0; kt < nK; kt++) {
        cpa_wait<STAGES - 2>();
        __syncthreads();
        if (kt + STAGES - 1 < nK) fill(kt + STAGES - 1, (kt + STAGES - 1) % STAGES);
        else cpa_commit();
        const uint32_t ab = sb + (kt % STAGES) * 32768;
        mma_core44(ab, ab + 16384, acc, wm, wn, l);
        __syncthreads();
    }
}

// ---------------------------------------------------------------------------
// Out-projection GEMM — 4 warps of 64x64 (validated round 14)
// ---------------------------------------------------------------------------
__global__ __launch_bounds__(128, 2) void gemm_out_kernel(
    const float* __restrict__ A, const float* __restrict__ B,
    float* __restrict__ C, const float* __restrict__ biasN)
{
    extern __shared__ float sm[];
    const uint32_t sb = su32(sm);
    const int tid = threadIdx.x, wid = tid >> 5, l = tid & 31;
    const int wm = wid >> 1, wn = wid & 1;
    int m0, n0; raster(blockIdx.x, m0, n0);

    float acc[4][8][4] = {};
    gemm_main4(A + (long long)m0 * DMODEL, B + (long long)n0 * DMODEL,
               sb, acc, tid, wm, wn, l);

#pragma unroll
    for (int mt = 0; mt < 4; mt++)
#pragma unroll
        for (int h = 0; h < 2; h++) {
            const long long row = m0 + wm * 64 + mt * 16 + (l >> 2) + h * 8;
            float* cr = C + row * DMODEL;
#pragma unroll
            for (int nt = 0; nt < 8; nt++) {
                int col = n0 + wn * 64 + nt * 8 + (l & 3) * 2;
                float2 o = {acc[mt][nt][2 * h] + biasN[col],
                            acc[mt][nt][2 * h + 1] + biasN[col + 1]};
                *(float2*)(cr + col) = o;
            }
        }
}

// ---------------------------------------------------------------------------
// Fused QKV GEMM — NOW 4 warps of 64x64 (rolling in the round-14 win).
// z: 0=Q (bias+rotary+round+perm), 1=K (same), 2=V (bias -> vt transposed)
// ---------------------------------------------------------------------------
__global__ __launch_bounds__(128, 2) void qkv_kernel(
    const float* __restrict__ xr,
    const float* __restrict__ wqr, const float* __restrict__ wkr,
    const float* __restrict__ wvr,
    float* __restrict__ qr, float* __restrict__ kr, float* __restrict__ vt,
    const float* __restrict__ bq, const float* __restrict__ bk,
    const float* __restrict__ bv)
{
    extern __shared__ float sm[];
    const uint32_t sb = su32(sm);
    const int tid = threadIdx.x, wid = tid >> 5, l = tid & 31;
    const int wm = wid >> 1, wn = wid & 1;
    const int z = blockIdx.z;
    int m0, n0; raster(blockIdx.x, m0, n0);

    const float* B = (z == 0) ? wqr : (z == 1) ? wkr : wvr;
    const float* biasN = (z == 0) ? bq : (z == 1) ? bk : bv;

    float acc[4][8][4] = {};
    gemm_main4(xr + (long long)m0 * DMODEL, B + (long long)n0 * DMODEL,
               sb, acc, tid, wm, wn, l);

    if (z < 2) {
        float* C = (z == 0) ? qr : kr;
#pragma unroll
        for (int mt = 0; mt < 4; mt++)
#pragma unroll
            for (int h = 0; h < 2; h++) {
                const long long row = m0 + wm * 64 + mt * 16 + (l >> 2) + h * 8;
                float* cr = C + row * DMODEL;
                if (wn == 0) {
                    // cols 0..63 of the 128-wide head tile: rotary block is 0..31
                    const int tok = (int)(row & (SEQ - 1));
                    const float* cs = g_cos + tok * 16;
                    const float* sn = g_sin + tok * 16;
#pragma unroll
                    for (int nt = 0; nt < 2; nt++) {
                        int i = nt * 8 + (l & 3) * 2;       // head-local re col (0..15)
                        int colr = n0 + i;
                        float re0 = acc[mt][nt][2 * h]     + biasN[colr];
                        float re1 = acc[mt][nt][2 * h + 1] + biasN[colr + 1];
                        float im0 = acc[mt][nt + 2][2 * h]     + biasN[colr + 16];
                        float im1 = acc[mt][nt + 2][2 * h + 1] + biasN[colr + 17];
                        float c0 = cs[i], s0 = sn[i], c1 = cs[i + 1], s1 = sn[i + 1];
                        int ob = n0 + 2 * i;
                        cr[permc(ob)]     = tf32r(re0 * c0 - im0 * s0);
                        cr[permc(ob + 1)] = tf32r(re0 * s0 + im0 * c0);
                        cr[permc(ob + 2)] = tf32r(re1 * c1 - im1 * s1);
                        cr[permc(ob + 3)] = tf32r(re1 * s1 + im1 * c1);
                    }
#pragma unroll
                    for (int nt = 4; nt < 8; nt++) {        // cols 32..63: plain
                        int col = n0 + nt * 8 + (l & 3) * 2;
                        cr[permc(col)]     = tf32r(acc[mt][nt][2 * h] + biasN[col]);
                        cr[permc(col + 1)] = tf32r(acc[mt][nt][2 * h + 1] + biasN[col + 1]);
                    }
                } else {
#pragma unroll
                    for (int nt = 0; nt < 8; nt++) {        // cols 64..127: plain
                        int col = n0 + 64 + nt * 8 + (l & 3) * 2;
                        cr[permc(col)]     = tf32r(acc[mt][nt][2 * h] + biasN[col]);
                        cr[permc(col + 1)] = tf32r(acc[mt][nt][2 * h + 1] + biasN[col + 1]);
                    }
                }
            }
    } else {
        // V: stage bias-added tile [s][d] in smem (pitch 133), write transposed
#pragma unroll
        for (int mt = 0; mt < 4; mt++)
#pragma unroll
            for (int h = 0; h < 2; h++) {
                int lrow = wm * 64 + mt * 16 + (l >> 2) + h * 8;
#pragma unroll
                for (int nt = 0; nt < 8; nt++) {
                    int col = wn * 64 + nt * 8 + (l & 3) * 2;
                    sm[lrow * 133 + col]     = acc[mt][nt][2 * h] + biasN[n0 + col];
                    sm[lrow * 133 + col + 1] = acc[mt][nt][2 * h + 1] + biasN[n0 + col + 1];
                }
            }
        __syncthreads();
        const int b = m0 >> 10, sBase = m0 & 1023, hd = n0 >> 7;
        const int d = tid;   // 0..127
        float* dpb = vt + ((long long)(b * NHEAD + hd) * HDIM + d) * SEQ + sBase;
#pragma unroll
        for (int shh = 0; shh < 2; shh++) {
            const int sh = shh << 6;
            float* dp = dpb + sh;
#pragma unroll
            for (int g16 = 0; g16 < 4; g16++)
#pragma unroll
                for (int a4 = 0; a4 < 4; a4++) {
                    int s0 = sh + g16 * 16;
                    float4 v;
                    v.x = tf32r(sm[(s0 + a4) * 133 + d]);
                    v.y = tf32r(sm[(s0 + 4 + a4) * 133 + d]);
                    v.z = tf32r(sm[(s0 + 8 + a4) * 133 + d]);
                    v.w = tf32r(sm[(s0 + 12 + a4) * 133 + d]);
                    *(float4*)(dp + g16 * 16 + a4 * 4) = v;
                }
        }
    }
}

// ---------------------------------------------------------------------------
// Flash attention v1 (round-7 version — best measured; 8-warp layout)
// ---------------------------------------------------------------------------
constexpr int SMEM_FLASH = 163840;
#define ATT_SCALE 0.08838834764831845f

__global__ __launch_bounds__(256, 1) void flash_kernel(
    const float* __restrict__ qr, const float* __restrict__ kr,
    const float* __restrict__ vt, const float* __restrict__ abias,
    float* __restrict__ outr)
{
    extern __shared__ float sm[];
    const uint32_t sb = su32(sm);
    __shared__ float rmax[128][4];
    __shared__ float rsum[128][4];

    const int tid = threadIdx.x, wid = tid >> 5, l = tid & 31;
    const int wm = wid >> 2, wn = wid & 3;
    const int bh = blockIdx.y, b = bh >> 5, h = bh & 31;
    const int q0 = blockIdx.x * 128;

    const float* qP = qr + ((long long)(b * SEQ + q0)) * DMODEL + h * HDIM;
    const float* kP = kr + (long long)b * SEQ * DMODEL + h * HDIM;
    const float* vP = vt + (long long)bh * HDIM * SEQ;
    const float* bP = abias + (long long)q0 * SEQ;
    float* oP = outr + ((long long)(b * SEQ + q0)) * DMODEL + h * HDIM;

#pragma unroll
    for (int s = 0; s < 4; s++)
#pragma unroll
        for (int i = 0; i < 4; i++) {
            int ch = tid + i * 256, r = ch >> 3, c = ch & 7;
            cpa(sb + s * 16384 + r * 128 + ((c ^ ((r & 1) << 2)) << 4),
                qP + (long long)r * DMODEL + s * 32 + c * 4);
        }
    cpa_commit();

    const uint32_t stb = sb + 131072;
    auto fillB = [&](uint32_t dst, const float* src, int ld, int koff) {
#pragma unroll
        for (int i = 0; i < 4; i++) {
            int ch = tid + i * 256, r = ch >> 3, c = ch & 7;
            cpa(dst + r * 128 + ((c ^ ((r & 1) << 2)) << 4),
                src + (long long)r * ld + koff + c * 4);
        }
        cpa_commit();
    };

    float oacc[4][4][4] = {};
    float mrun[4][2], lrun[4][2];
#pragma unroll
    for (int mt = 0; mt < 4; mt++)
#pragma unroll
        for (int hh = 0; hh < 2; hh++) { mrun[mt][hh] = -1e30f; lrun[mt][hh] = 0.0f; }

    cpa_wait<0>();
    __syncthreads();

    for (int st = 0; st < 8; st++) {
        const int s0 = st * 128;
        float sacc[4][4][4] = {};

        fillB(stb, kP + (long long)s0 * DMODEL, DMODEL, 0);
#pragma unroll
        for (int kt = 0; kt < 4; kt++) {
            if (kt < 3) {
                fillB(stb + ((kt + 1) & 1) * 16384, kP + (long long)s0 * DMODEL,
                      DMODEL, (kt + 1) * 32);
                cpa_wait<1>();
            } else cpa_wait<0>();
            __syncthreads();
            mma_core(sb + kt * 16384, stb + (kt & 1) * 16384, sacc, wm, wn, l);
            __syncthreads();
        }

        fillB(stb, vP, SEQ, s0);

#pragma unroll
        for (int mt = 0; mt < 4; mt++)
#pragma unroll
            for (int hh = 0; hh < 2; hh++) {
                int lrow = wm * 64 + mt * 16 + (l >> 2) + hh * 8;
                const float* br = bP + (long long)lrow * SEQ + s0;
#pragma unroll
                for (int nt = 0; nt < 4; nt++) {
                    int col = wn * 32 + nt * 8 + (l & 3) * 2;
                    float2 bv = *(const float2*)(br + col);
                    sacc[mt][nt][2 * hh]     = sacc[mt][nt][2 * hh] * ATT_SCALE + bv.x;
                    sacc[mt][nt][2 * hh + 1] = sacc[mt][nt][2 * hh + 1] * ATT_SCALE + bv.y;
                }
            }

#pragma unroll
        for (int mt = 0; mt < 4; mt++)
#pragma unroll
            for (int hh = 0; hh < 2; hh++) {
                int lrow = wm * 64 + mt * 16 + (l >> 2) + hh * 8;
                float mx = -1e30f;
#pragma unroll
                for (int nt = 0; nt < 4; nt++)
                    mx = fmaxf(mx, fmaxf(sacc[mt][nt][2 * hh], sacc[mt][nt][2 * hh + 1]));
                mx = fmaxf(mx, __shfl_xor_sync(~0u, mx, 1));
                mx = fmaxf(mx, __shfl_xor_sync(~0u, mx, 2));
                if ((l & 3) == 0) rmax[lrow][wn] = mx;
            }
        __syncthreads();

        float alpha[4][2], mnew[4][2];
#pragma unroll
        for (int mt = 0; mt < 4; mt++)
#pragma unroll
            for (int hh = 0; hh < 2; hh++) {
                int lrow = wm * 64 + mt * 16 + (l >> 2) + hh * 8;
                float Mt = fmaxf(fmaxf(rmax[lrow][0], rmax[lrow][1]),
                                 fmaxf(rmax[lrow][2], rmax[lrow][3]));
                float mn = fmaxf(mrun[mt][hh], Mt);
                alpha[mt][hh] = __expf(mrun[mt][hh] - mn);
                mnew[mt][hh] = mn;
                mrun[mt][hh] = mn;
            }

#pragma unroll
        for (int mt = 0; mt < 4; mt++)
#pragma unroll
            for (int hh = 0; hh < 2; hh++) {
                int lrow = wm * 64 + mt * 16 + (l >> 2) + hh * 8;
                float ssum = 0.0f;
#pragma unroll
                for (int nt = 0; nt < 4; nt++) {
                    int col = wn * 32 + nt * 8 + (l & 3) * 2;
                    float p0 = __expf(sacc[mt][nt][2 * hh] - mnew[mt][hh]);
                    float p1 = __expf(sacc[mt][nt][2 * hh + 1] - mnew[mt][hh]);
                    ssum += p0 + p1;
#pragma unroll
                    for (int j = 0; j < 2; j++) {
                        int cc = col + j;
                        int w = permc(cc) & 31;
                        int widx = 16384 + (cc >> 5) * 4096 + lrow * 32 +
                                   (((w >> 2) ^ ((lrow & 1) << 2)) << 2) + (w & 3);
                        sm[widx] = tf32r(j == 0 ? p0 : p1);
                    }
                }
                ssum += __shfl_xor_sync(~0u, ssum, 1);
                ssum += __shfl_xor_sync(~0u, ssum, 2);
                if ((l & 3) == 0) rsum[lrow][wn] = ssum;
            }
        __syncthreads();

#pragma unroll
        for (int mt = 0; mt < 4; mt++)
#pragma unroll
            for (int hh = 0; hh < 2; hh++) {
                int lrow = wm * 64 + mt * 16 + (l >> 2) + hh * 8;
                float St = rsum[lrow][0] + rsum[lrow][1] + rsum[lrow][2] + rsum[lrow][3];
                lrun[mt][hh] = lrun[mt][hh] * alpha[mt][hh] + St;
                float a = alpha[mt][hh];
#pragma unroll
                for (int nt = 0; nt < 4; nt++) {
                    oacc[mt][nt][2 * hh] *= a;
                    oacc[mt][nt][2 * hh + 1] *= a;
                }
            }

#pragma unroll
        for (int kt = 0; kt < 4; kt++) {
            if (kt < 3) {
                fillB(stb + ((kt + 1) & 1) * 16384, vP, SEQ, s0 + (kt + 1) * 32);
                cpa_wait<1>();
            } else cpa_wait<0>();
            __syncthreads();
            mma_core(sb + 65536 + kt * 16384, stb + (kt & 1) * 16384, oacc, wm, wn, l);
            __syncthreads();
        }
    }

#pragma unroll
    for (int mt = 0; mt < 4; mt++)
#pragma unroll
        for (int hh = 0; hh < 2; hh++) {
            int lrow = wm * 64 + mt * 16 + (l >> 2) + hh * 8;
            float inv = 1.0f / lrun[mt][hh];
            float* orow = oP + (long long)lrow * DMODEL;
#pragma unroll
            for (int nt = 0; nt < 4; nt++) {
                int d = wn * 32 + nt * 8 + (l & 3) * 2;
                orow[permc(d)]     = tf32r(oacc[mt][nt][2 * hh] * inv);
                orow[permc(d + 1)] = tf32r(oacc[mt][nt][2 * hh + 1] * inv);
            }
        }
}

// ---------------- prep kernels ----------------------------------------------
__global__ void rotary_table_kernel() {
    int idx = blockIdx.x * blockDim.x + threadIdx.x;
    if (idx >= SEQ * 16) return;
    int s = idx >> 4, i = idx & 15;
    double inv = pow(10000.0, -((double)(2 * i)) / 32.0);
    double ang = (double)(MAX_POS - SEQ + s) * inv;
    g_cos[idx] = (float)cos(ang);
    g_sin[idx] = (float)sin(ang);
}

__global__ void rp_kernel(const float* __restrict__ in, float* __restrict__ out, int n4) {
    int i = blockIdx.x * blockDim.x + threadIdx.x;
    if (i >= n4) return;
    int r = i >> 10, c = (i & 1023) * 4;
    float4 v = *(const float4*)(in + (long long)r * 4096 + c);
    float* o = out + (long long)r * 4096;
    o[permc(c)]     = tf32r(v.x);
    o[permc(c + 1)] = tf32r(v.y);
    o[permc(c + 2)] = tf32r(v.z);
    o[permc(c + 3)] = tf32r(v.w);
}

__global__ void wt_all_kernel(const float* __restrict__ wq, const float* __restrict__ wk,
                              const float* __restrict__ wv, const float* __restrict__ wo,
                              float* __restrict__ oq, float* __restrict__ ok,
                              float* __restrict__ ov, float* __restrict__ oo) {
    __shared__ float t[32][33];
    const int z = blockIdx.z;
    const float* w = (z == 0) ? wq : (z == 1) ? wk : (z == 2) ? wv : wo;
    float* o = (z == 0) ? oq : (z == 1) ? ok : (z == 2) ? ov : oo;
    int k0 = blockIdx.y * 32, n0 = blockIdx.x * 32;
    int tx = threadIdx.x, ty = threadIdx.y;
#pragma unroll
    for (int i = 0; i < 4; i++)
        t[ty + i * 8][tx] = w[(long long)(k0 + ty + i * 8) * 4096 + n0 + tx];
    __syncthreads();
#pragma unroll
    for (int i = 0; i < 4; i++) {
        int n = n0 + ty + i * 8, k = k0 + tx;
        o[(long long)n * 4096 + permc(k)] = tf32r(t[tx][ty + i * 8]);
    }
}

// ---------------- host ------------------------------------------------------
extern "C" void kernel_launch(void* const* d_in, const int* in_sizes, int n_in,
                              void* d_out, int out_size) {
    (void)in_sizes; (void)n_in; (void)out_size;
    const float* x    = (const float*)d_in[0];
    const float* abia = (const float*)d_in[1];
    const float* wq   = (const float*)d_in[2];
    const float* bq   = (const float*)d_in[3];
    const float* wk   = (const float*)d_in[4];
    const float* bk   = (const float*)d_in[5];
    const float* wv   = (const float*)d_in[6];
    const float* bv   = (const float*)d_in[7];
    const float* wo   = (const float*)d_in[8];
    const float* bo   = (const float*)d_in[9];
    float* out = (float*)d_out;

    void* p;
    cudaGetSymbolAddress(&p, g_xr);  float* xr  = (float*)p;
    cudaGetSymbolAddress(&p, g_wqr); float* wqr = (float*)p;
    cudaGetSymbolAddress(&p, g_wkr); float* wkr = (float*)p;
    cudaGetSymbolAddress(&p, g_wvr); float* wvr = (float*)p;
    cudaGetSymbolAddress(&p, g_wor); float* wor = (float*)p;
    cudaGetSymbolAddress(&p, g_qr);  float* qr  = (float*)p;
    cudaGetSymbolAddress(&p, g_kr);  float* kr  = (float*)p;
    cudaGetSymbolAddress(&p, g_vt);  float* vt  = (float*)p;
    float* orr = xr;   // xr dead after QKV GEMMs -> reuse for flash output

    cudaFuncSetAttribute(gemm_out_kernel, cudaFuncAttributeMaxDynamicSharedMemorySize, SMEM_GEMM);
    cudaFuncSetAttribute(qkv_kernel,      cudaFuncAttributeMaxDynamicSharedMemorySize, SMEM_GEMM);
    cudaFuncSetAttribute(flash_kernel,    cudaFuncAttributeMaxDynamicSharedMemorySize, SMEM_FLASH);

    rotary_table_kernel<<<(SEQ * 16 + 255) / 256, 256>>>();
    rp_kernel<<<(TOKENS * 1024 + 255) / 256, 256>>>(x, xr, TOKENS * 1024);
    wt_all_kernel<<<dim3(128, 128, 4), dim3(32, 8)>>>(wq, wk, wv, wo, wqr, wkr, wvr, wor);

    // 4-warp 64x64 config everywhere GEMM-shaped
    qkv_kernel<<<dim3(1024, 1, 3), 128, SMEM_GEMM>>>(
        xr, wqr, wkr, wvr, qr, kr, vt, bq, bk, bv);

    flash_kernel<<<dim3(8, BATCHN * NHEAD), 256, SMEM_FLASH>>>(qr, kr, vt, abia, orr);

    gemm_out_kernel<<<dim3(1024), 128, SMEM_GEMM>>>(orr, wor, out, bo);
}

// round 16
// speedup vs baseline: 1.5261x; 1.5261x over previous
#include <cuda_runtime.h>
#include <cstdint>
#include <math.h>

#define BATCHN 4
#define SEQ    1024
#define DMODEL 4096
#define NHEAD  32
#define HDIM   128
#define TOKENS 4096
#define MAX_POS 10000

// ---------------- scratch (device globals; malloc banned) ------------------
__device__ float g_xr [(size_t)TOKENS * DMODEL];
__device__ float g_wqr[(size_t)DMODEL * DMODEL];
__device__ float g_wkr[(size_t)DMODEL * DMODEL];
__device__ float g_wvr[(size_t)DMODEL * DMODEL];
__device__ float g_wor[(size_t)DMODEL * DMODEL];
__device__ float g_qr [(size_t)TOKENS * DMODEL];
__device__ float g_kr [(size_t)TOKENS * DMODEL];
__device__ float g_vt [(size_t)BATCHN * NHEAD * HDIM * SEQ];
__device__ float g_cos[SEQ * 16];
__device__ float g_sin[SEQ * 16];

// ---------------- helpers ---------------------------------------------------
__device__ __forceinline__ uint32_t su32(const void* p) {
    return (uint32_t)__cvta_generic_to_shared(p);
}
__device__ __forceinline__ float tf32r(float x) {
    uint32_t u;
    asm("cvt.rna.tf32.f32 %0, %1;" : "=r"(u) : "f"(x));
    return __uint_as_float(u);
}
__device__ __forceinline__ int permc(int k) {
    int kk = k & 15;
    return (k & ~15) | ((kk & 3) << 2) | (kk >> 2);
}
__device__ __forceinline__ void cpa(uint32_t s, const void* g) {
    asm volatile("cp.async.cg.shared.global [%0], [%1], 16;" :: "r"(s), "l"(g));
}
__device__ __forceinline__ void cpa_commit() {
    asm volatile("cp.async.commit_group;" ::: "memory");
}
template <int N> __device__ __forceinline__ void cpa_wait() {
    asm volatile("cp.async.wait_group %0;" :: "n"(N) : "memory");
}
__device__ __forceinline__ void lds4(uint32_t* v, uint32_t a) {
    asm volatile("ld.shared.v4.b32 {%0,%1,%2,%3}, [%4];"
                 : "=r"(v[0]), "=r"(v[1]), "=r"(v[2]), "=r"(v[3]) : "r"(a));
}
__device__ __forceinline__ void mma8(float* c, uint32_t a0, uint32_t a1, uint32_t a2,
                                     uint32_t a3, uint32_t b0, uint32_t b1) {
    asm volatile(
        "mma.sync.aligned.m16n8k8.row.col.f32.tf32.tf32.f32 "
        "{%0,%1,%2,%3},{%4,%5,%6,%7},{%8,%9},{%0,%1,%2,%3};"
        : "+f"(c[0]), "+f"(c[1]), "+f"(c[2]), "+f"(c[3])
        : "r"(a0), "r"(a1), "r"(a2), "r"(a3), "r"(b0), "r"(b1));
}

// 128x128x32 warp-tile mma core (8 warps 2x4, warp 64x32) — proven config
__device__ __forceinline__ void mma_core(uint32_t ab, uint32_t bb,
                                         float acc[4][4][4], int wm, int wn, int l) {
#pragma unroll
    for (int g = 0; g < 2; g++) {
        uint32_t bfr[4][4];
#pragma unroll
        for (int nt = 0; nt < 4; nt++) {
            int r = wn * 32 + nt * 8 + (l >> 2);
            lds4(bfr[nt], bb + r * 128 + (((g * 4 + (l & 3)) ^ ((r & 1) << 2)) << 4));
        }
#pragma unroll
        for (int mt = 0; mt < 4; mt++) {
            int r0 = wm * 64 + mt * 16 + (l >> 2), r1 = r0 + 8;
            uint32_t a0[4], a1[4];
            lds4(a0, ab + r0 * 128 + (((g * 4 + (l & 3)) ^ ((r0 & 1) << 2)) << 4));
            lds4(a1, ab + r1 * 128 + (((g * 4 + (l & 3)) ^ ((r1 & 1) << 2)) << 4));
#pragma unroll
            for (int nt = 0; nt < 4; nt++)
                mma8(acc[mt][nt], a0[0], a1[0], a0[1], a1[1], bfr[nt][0], bfr[nt][1]);
#pragma unroll
            for (int nt = 0; nt < 4; nt++)
                mma8(acc[mt][nt], a0[2], a1[2], a0[3], a1[3], bfr[nt][2], bfr[nt][3]);
        }
    }
}

// 128x128x32 with 4 warps (2x2) of 64x64 — use ONLY with light epilogues
__device__ __forceinline__ void mma_core44(uint32_t ab, uint32_t bb,
                                           float acc[4][8][4], int wm, int wn, int l) {
#pragma unroll
    for (int g = 0; g < 2; g++) {
        uint32_t bfr[8][4];
#pragma unroll
        for (int nt = 0; nt < 8; nt++) {
            int r = wn * 64 + nt * 8 + (l >> 2);
            lds4(bfr[nt], bb + r * 128 + (((g * 4 + (l & 3)) ^ ((r & 1) << 2)) << 4));
        }
#pragma unroll
        for (int mt = 0; mt < 4; mt++) {
            int r0 = wm * 64 + mt * 16 + (l >> 2), r1 = r0 + 8;
            uint32_t a0[4], a1[4];
            lds4(a0, ab + r0 * 128 + (((g * 4 + (l & 3)) ^ ((r0 & 1) << 2)) << 4));
            lds4(a1, ab + r1 * 128 + (((g * 4 + (l & 3)) ^ ((r1 & 1) << 2)) << 4));
#pragma unroll
            for (int nt = 0; nt < 8; nt++)
                mma8(acc[mt][nt], a0[0], a1[0], a0[1], a1[1], bfr[nt][0], bfr[nt][1]);
#pragma unroll
            for (int nt = 0; nt < 8; nt++)
                mma8(acc[mt][nt], a0[2], a1[2], a0[3], a1[3], bfr[nt][2], bfr[nt][3]);
        }
    }
}

constexpr int STAGES = 3;
constexpr int SMEM_GEMM = STAGES * 32768;   // 96KB

__device__ __forceinline__ void raster(int pid, int& m0, int& n0) {
    const int gs = 8 * 32;
    int gid = pid / gs, r = pid - gid * gs;
    m0 = (gid * 8 + (r & 7)) * 128;
    n0 = (r >> 3) * 128;
}

// 256-thread GEMM mainloop (round-7 proven form)
__device__ __forceinline__ void gemm_main(
    const float* A, int lda, const float* B, int ldb, int K,
    uint32_t sb, float acc[4][4][4], int tid, int wm, int wn, int l)
{
    const int nK = K / 32;
    auto fill = [&](int kt, int s) {
        const uint32_t ab = sb + s * 32768;
        const float* ag = A + kt * 32;
        const float* bg = B + kt * 32;
#pragma unroll
        for (int i = 0; i < 4; i++) {
            int ch = tid + i * 256, r = ch >> 3, c = ch & 7;
            cpa(ab + r * 128 + ((c ^ ((r & 1) << 2)) << 4),
                ag + (long long)r * lda + c * 4);
        }
#pragma unroll
        for (int i = 0; i < 4; i++) {
            int ch = tid + i * 256, r = ch >> 3, c = ch & 7;
            cpa(ab + 16384 + r * 128 + ((c ^ ((r & 1) << 2)) << 4),
                bg + (long long)r * ldb + c * 4);
        }
        cpa_commit();
    };
    for (int s = 0; s < STAGES - 1; s++) fill(s, s);
    for (int kt = 0; kt < nK; kt++) {
        cpa_wait<STAGES - 2>();
        __syncthreads();
        if (kt + STAGES - 1 < nK) fill(kt + STAGES - 1, (kt + STAGES - 1) % STAGES);
        else cpa_commit();
        const uint32_t ab = sb + (kt % STAGES) * 32768;
        mma_core(ab, ab + 16384, acc, wm, wn, l);
        __syncthreads();
    }
}

// ---------------------------------------------------------------------------
// Out-projection GEMM — 4 warps of 64x64 (validated round 14; light epilogue)
// ---------------------------------------------------------------------------
__global__ __launch_bounds__(128, 2) void gemm_out_kernel(
    const float* __restrict__ A, const float* __restrict__ B,
    float* __restrict__ C, const float* __restrict__ biasN)
{
    extern __shared__ float sm[];
    const uint32_t sb = su32(sm);
    const int tid = threadIdx.x, wid = tid >> 5, l = tid & 31;
    const int wm = wid >> 1, wn = wid & 1;
    int m0, n0; raster(blockIdx.x, m0, n0);

    const float* Ap = A + (long long)m0 * DMODEL;
    const float* Bp = B + (long long)n0 * DMODEL;

    float acc[4][8][4] = {};
    const int nK = DMODEL / 32;
    auto fill = [&](int kt, int s) {
        const uint32_t ab = sb + s * 32768;
        const float* ag = Ap + kt * 32;
        const float* bg = Bp + kt * 32;
#pragma unroll
        for (int i = 0; i < 8; i++) {
            int ch = tid + i * 128, r = ch >> 3, c = ch & 7;
            cpa(ab + r * 128 + ((c ^ ((r & 1) << 2)) << 4),
                ag + (long long)r * DMODEL + c * 4);
        }
#pragma unroll
        for (int i = 0; i < 8; i++) {
            int ch = tid + i * 128, r = ch >> 3, c = ch & 7;
            cpa(ab + 16384 + r * 128 + ((c ^ ((r & 1) << 2)) << 4),
                bg + (long long)r * DMODEL + c * 4);
        }
        cpa_commit();
    };
    for (int s = 0; s < STAGES - 1; s++) fill(s, s);
    for (int kt = 0; kt < nK; kt++) {
        cpa_wait<STAGES - 2>();
        __syncthreads();
        if (kt + STAGES - 1 < nK) fill(kt + STAGES - 1, (kt + STAGES - 1) % STAGES);
        else cpa_commit();
        const uint32_t ab = sb + (kt % STAGES) * 32768;
        mma_core44(ab, ab + 16384, acc, wm, wn, l);
        __syncthreads();
    }

#pragma unroll
    for (int mt = 0; mt < 4; mt++)
#pragma unroll
        for (int h = 0; h < 2; h++) {
            const long long row = m0 + wm * 64 + mt * 16 + (l >> 2) + h * 8;
            float* cr = C + row * DMODEL;
#pragma unroll
            for (int nt = 0; nt < 8; nt++) {
                int col = n0 + wn * 64 + nt * 8 + (l & 3) * 2;
                float2 o = {acc[mt][nt][2 * h] + biasN[col],
                            acc[mt][nt][2 * h + 1] + biasN[col + 1]};
                *(float2*)(cr + col) = o;
            }
        }
}

// ---------------------------------------------------------------------------
// Fused QKV GEMM — 8 warps / 256 threads (proven; heavy epilogue needs 16 warps/SM)
// z: 0=Q (bias+rotary+round+perm), 1=K (same), 2=V (bias -> vt transposed)
// ---------------------------------------------------------------------------
__global__ __launch_bounds__(256, 2) void qkv_kernel(
    const float* __restrict__ xr,
    const float* __restrict__ wqr, const float* __restrict__ wkr,
    const float* __restrict__ wvr,
    float* __restrict__ qr, float* __restrict__ kr, float* __restrict__ vt,
    const float* __restrict__ bq, const float* __restrict__ bk,
    const float* __restrict__ bv)
{
    extern __shared__ float sm[];
    const uint32_t sb = su32(sm);
    const int tid = threadIdx.x, wid = tid >> 5, l = tid & 31;
    const int wm = wid >> 2, wn = wid & 3;
    const int z = blockIdx.z;
    int m0, n0; raster(blockIdx.x, m0, n0);

    const float* B = (z == 0) ? wqr : (z == 1) ? wkr : wvr;
    const float* biasN = (z == 0) ? bq : (z == 1) ? bk : bv;

    float acc[4][4][4] = {};
    gemm_main(xr + (long long)m0 * DMODEL, DMODEL, B + (long long)n0 * DMODEL, DMODEL,
              DMODEL, sb, acc, tid, wm, wn, l);

    if (z < 2) {
        float* C = (z == 0) ? qr : kr;
#pragma unroll
        for (int mt = 0; mt < 4; mt++)
#pragma unroll
            for (int h = 0; h < 2; h++) {
                const long long row = m0 + wm * 64 + mt * 16 + (l >> 2) + h * 8;
                float* cr = C + row * DMODEL;
                if (wn == 0) {
                    const int tok = (int)(row & (SEQ - 1));
                    const float* cs = g_cos + tok * 16;
                    const float* sn = g_sin + tok * 16;
#pragma unroll
                    for (int nt = 0; nt < 2; nt++) {
                        int i = nt * 8 + (l & 3) * 2;
                        int colr = n0 + i;
                        float re0 = acc[mt][nt][2 * h]     + biasN[colr];
                        float re1 = acc[mt][nt][2 * h + 1] + biasN[colr + 1];
                        float im0 = acc[mt][nt + 2][2 * h]     + biasN[colr + 16];
                        float im1 = acc[mt][nt + 2][2 * h + 1] + biasN[colr + 17];
                        float c0 = cs[i], s0 = sn[i], c1 = cs[i + 1], s1 = sn[i + 1];
                        int ob = n0 + 2 * i;
                        cr[permc(ob)]     = tf32r(re0 * c0 - im0 * s0);
                        cr[permc(ob + 1)] = tf32r(re0 * s0 + im0 * c0);
                        cr[permc(ob + 2)] = tf32r(re1 * c1 - im1 * s1);
                        cr[permc(ob + 3)] = tf32r(re1 * s1 + im1 * c1);
                    }
                } else {
#pragma unroll
                    for (int nt = 0; nt < 4; nt++) {
                        int col = n0 + wn * 32 + nt * 8 + (l & 3) * 2;
                        cr[permc(col)]     = tf32r(acc[mt][nt][2 * h] + biasN[col]);
                        cr[permc(col + 1)] = tf32r(acc[mt][nt][2 * h + 1] + biasN[col + 1]);
                    }
                }
            }
    } else {
        // V: stage bias-added tile [s][d] in smem (pitch 133), write transposed
#pragma unroll
        for (int mt = 0; mt < 4; mt++)
#pragma unroll
            for (int h = 0; h < 2; h++) {
                int lrow = wm * 64 + mt * 16 + (l >> 2) + h * 8;
#pragma unroll
                for (int nt = 0; nt < 4; nt++) {
                    int col = wn * 32 + nt * 8 + (l & 3) * 2;
                    sm[lrow * 133 + col]     = acc[mt][nt][2 * h] + biasN[n0 + col];
                    sm[lrow * 133 + col + 1] = acc[mt][nt][2 * h + 1] + biasN[n0 + col + 1];
                }
            }
        __syncthreads();
        const int b = m0 >> 10, sBase = m0 & 1023, hd = n0 >> 7;
        const int d = tid >> 1, sh = (tid & 1) << 6;
        float* dp = vt + ((long long)(b * NHEAD + hd) * HDIM + d) * SEQ + sBase + sh;
#pragma unroll
        for (int g16 = 0; g16 < 4; g16++)
#pragma unroll
            for (int a4 = 0; a4 < 4; a4++) {
                int s0 = sh + g16 * 16;
                float4 v;
                v.x = tf32r(sm[(s0 + a4) * 133 + d]);
                v.y = tf32r(sm[(s0 + 4 + a4) * 133 + d]);
                v.z = tf32r(sm[(s0 + 8 + a4) * 133 + d]);
                v.w = tf32r(sm[(s0 + 12 + a4) * 133 + d]);
                *(float4*)(dp + g16 * 16 + a4 * 4) = v;
            }
    }
}

// ---------------------------------------------------------------------------
// Flash attention v1 (round-7 version — best measured; 8-warp layout)
// ---------------------------------------------------------------------------
constexpr int SMEM_FLASH = 163840;
#define ATT_SCALE 0.08838834764831845f

__global__ __launch_bounds__(256, 1) void flash_kernel(
    const float* __restrict__ qr, const float* __restrict__ kr,
    const float* __restrict__ vt, const float* __restrict__ abias,
    float* __restrict__ outr)
{
    extern __shared__ float sm[];
    const uint32_t sb = su32(sm);
    __shared__ float rmax[128][4];
    __shared__ float rsum[128][4];

    const int tid = threadIdx.x, wid = tid >> 5, l = tid & 31;
    const int wm = wid >> 2, wn = wid & 3;
    const int bh = blockIdx.y, b = bh >> 5, h = bh & 31;
    const int q0 = blockIdx.x * 128;

    const float* qP = qr + ((long long)(b * SEQ + q0)) * DMODEL + h * HDIM;
    const float* kP = kr + (long long)b * SEQ * DMODEL + h * HDIM;
    const float* vP = vt + (long long)bh * HDIM * SEQ;
    const float* bP = abias + (long long)q0 * SEQ;
    float* oP = outr + ((long long)(b * SEQ + q0)) * DMODEL + h * HDIM;

#pragma unroll
    for (int s = 0; s < 4; s++)
#pragma unroll
        for (int i = 0; i < 4; i++) {
            int ch = tid + i * 256, r = ch >> 3, c = ch & 7;
            cpa(sb + s * 16384 + r * 128 + ((c ^ ((r & 1) << 2)) << 4),
                qP + (long long)r * DMODEL + s * 32 + c * 4);
        }
    cpa_commit();

    const uint32_t stb = sb + 131072;
    auto fillB = [&](uint32_t dst, const float* src, int ld, int koff) {
#pragma unroll
        for (int i = 0; i < 4; i++) {
            int ch = tid + i * 256, r = ch >> 3, c = ch & 7;
            cpa(dst + r * 128 + ((c ^ ((r & 1) << 2)) << 4),
                src + (long long)r * ld + koff + c * 4);
        }
        cpa_commit();
    };

    float oacc[4][4][4] = {};
    float mrun[4][2], lrun[4][2];
#pragma unroll
    for (int mt = 0; mt < 4; mt++)
#pragma unroll
        for (int hh = 0; hh < 2; hh++) { mrun[mt][hh] = -1e30f; lrun[mt][hh] = 0.0f; }

    cpa_wait<0>();
    __syncthreads();

    for (int st = 0; st < 8; st++) {
        const int s0 = st * 128;
        float sacc[4][4][4] = {};

        fillB(stb, kP + (long long)s0 * DMODEL, DMODEL, 0);
#pragma unroll
        for (int kt = 0; kt < 4; kt++) {
            if (kt < 3) {
                fillB(stb + ((kt + 1) & 1) * 16384, kP + (long long)s0 * DMODEL,
                      DMODEL, (kt + 1) * 32);
                cpa_wait<1>();
            } else cpa_wait<0>();
            __syncthreads();
            mma_core(sb + kt * 16384, stb + (kt & 1) * 16384, sacc, wm, wn, l);
            __syncthreads();
        }

        fillB(stb, vP, SEQ, s0);

#pragma unroll
        for (int mt = 0; mt < 4; mt++)
#pragma unroll
            for (int hh = 0; hh < 2; hh++) {
                int lrow = wm * 64 + mt * 16 + (l >> 2) + hh * 8;
                const float* br = bP + (long long)lrow * SEQ + s0;
#pragma unroll
                for (int nt = 0; nt < 4; nt++) {
                    int col = wn * 32 + nt * 8 + (l & 3) * 2;
                    float2 bv = *(const float2*)(br + col);
                    sacc[mt][nt][2 * hh]     = sacc[mt][nt][2 * hh] * ATT_SCALE + bv.x;
                    sacc[mt][nt][2 * hh + 1] = sacc[mt][nt][2 * hh + 1] * ATT_SCALE + bv.y;
                }
            }

#pragma unroll
        for (int mt = 0; mt < 4; mt++)
#pragma unroll
            for (int hh = 0; hh < 2; hh++) {
                int lrow = wm * 64 + mt * 16 + (l >> 2) + hh * 8;
                float mx = -1e30f;
#pragma unroll
                for (int nt = 0; nt < 4; nt++)
                    mx = fmaxf(mx, fmaxf(sacc[mt][nt][2 * hh], sacc[mt][nt][2 * hh + 1]));
                mx = fmaxf(mx, __shfl_xor_sync(~0u, mx, 1));
                mx = fmaxf(mx, __shfl_xor_sync(~0u, mx, 2));
                if ((l & 3) == 0) rmax[lrow][wn] = mx;
            }
        __syncthreads();

        float alpha[4][2], mnew[4][2];
#pragma unroll
        for (int mt = 0; mt < 4; mt++)
#pragma unroll
            for (int hh = 0; hh < 2; hh++) {
                int lrow = wm * 64 + mt * 16 + (l >> 2) + hh * 8;
                float Mt = fmaxf(fmaxf(rmax[lrow][0], rmax[lrow][1]),
                                 fmaxf(rmax[lrow][2], rmax[lrow][3]));
                float mn = fmaxf(mrun[mt][hh], Mt);
                alpha[mt][hh] = __expf(mrun[mt][hh] - mn);
                mnew[mt][hh] = mn;
                mrun[mt][hh] = mn;
            }

#pragma unroll
        for (int mt = 0; mt < 4; mt++)
#pragma unroll
            for (int hh = 0; hh < 2; hh++) {
                int lrow = wm * 64 + mt * 16 + (l >> 2) + hh * 8;
                float ssum = 0.0f;
#pragma unroll
                for (int nt = 0; nt < 4; nt++) {
                    int col = wn * 32 + nt * 8 + (l & 3) * 2;
                    float p0 = __expf(sacc[mt][nt][2 * hh] - mnew[mt][hh]);
                    float p1 = __expf(sacc[mt][nt][2 * hh + 1] - mnew[mt][hh]);
                    ssum += p0 + p1;
#pragma unroll
                    for (int j = 0; j < 2; j++) {
                        int cc = col + j;
                        int w = permc(cc) & 31;
                        int widx = 16384 + (cc >> 5) * 4096 + lrow * 32 +
                                   (((w >> 2) ^ ((lrow & 1) << 2)) << 2) + (w & 3);
                        sm[widx] = tf32r(j == 0 ? p0 : p1);
                    }
                }
                ssum += __shfl_xor_sync(~0u, ssum, 1);
                ssum += __shfl_xor_sync(~0u, ssum, 2);
                if ((l & 3) == 0) rsum[lrow][wn] = ssum;
            }
        __syncthreads();

#pragma unroll
        for (int mt = 0; mt < 4; mt++)
#pragma unroll
            for (int hh = 0; hh < 2; hh++) {
                int lrow = wm * 64 + mt * 16 + (l >> 2) + hh * 8;
                float St = rsum[lrow][0] + rsum[lrow][1] + rsum[lrow][2] + rsum[lrow][3];
                lrun[mt][hh] = lrun[mt][hh] * alpha[mt][hh] + St;
                float a = alpha[mt][hh];
#pragma unroll
                for (int nt = 0; nt < 4; nt++) {
                    oacc[mt][nt][2 * hh] *= a;
                    oacc[mt][nt][2 * hh + 1] *= a;
                }
            }

#pragma unroll
        for (int kt = 0; kt < 4; kt++) {
            if (kt < 3) {
                fillB(stb + ((kt + 1) & 1) * 16384, vP, SEQ, s0 + (kt + 1) * 32);
                cpa_wait<1>();
            } else cpa_wait<0>();
            __syncthreads();
            mma_core(sb + 65536 + kt * 16384, stb + (kt & 1) * 16384, oacc, wm, wn, l);
            __syncthreads();
        }
    }

#pragma unroll
    for (int mt = 0; mt < 4; mt++)
#pragma unroll
        for (int hh = 0; hh < 2; hh++) {
            int lrow = wm * 64 + mt * 16 + (l >> 2) + hh * 8;
            float inv = 1.0f / lrun[mt][hh];
            float* orow = oP + (long long)lrow * DMODEL;
#pragma unroll
            for (int nt = 0; nt < 4; nt++) {
                int d = wn * 32 + nt * 8 + (l & 3) * 2;
                orow[permc(d)]     = tf32r(oacc[mt][nt][2 * hh] * inv);
                orow[permc(d + 1)] = tf32r(oacc[mt][nt][2 * hh + 1] * inv);
            }
        }
}

// ---------------- prep kernels ----------------------------------------------
__global__ void rotary_table_kernel() {
    int idx = blockIdx.x * blockDim.x + threadIdx.x;
    if (idx >= SEQ * 16) return;
    int s = idx >> 4, i = idx & 15;
    double inv = pow(10000.0, -((double)(2 * i)) / 32.0);
    double ang = (double)(MAX_POS - SEQ + s) * inv;
    g_cos[idx] = (float)cos(ang);
    g_sin[idx] = (float)sin(ang);
}

__global__ void rp_kernel(const float* __restrict__ in, float* __restrict__ out, int n4) {
    int i = blockIdx.x * blockDim.x + threadIdx.x;
    if (i >= n4) return;
    int r = i >> 10, c = (i & 1023) * 4;
    float4 v = *(const float4*)(in + (long long)r * 4096 + c);
    float* o = out + (long long)r * 4096;
    o[permc(c)]     = tf32r(v.x);
    o[permc(c + 1)] = tf32r(v.y);
    o[permc(c + 2)] = tf32r(v.z);
    o[permc(c + 3)] = tf32r(v.w);
}

__global__ void wt_all_kernel(const float* __restrict__ wq, const float* __restrict__ wk,
                              const float* __restrict__ wv, const float* __restrict__ wo,
                              float* __restrict__ oq, float* __restrict__ ok,
                              float* __restrict__ ov, float* __restrict__ oo) {
    __shared__ float t[32][33];
    const int z = blockIdx.z;
    const float* w = (z == 0) ? wq : (z == 1) ? wk : (z == 2) ? wv : wo;
    float* o = (z == 0) ? oq : (z == 1) ? ok : (z == 2) ? ov : oo;
    int k0 = blockIdx.y * 32, n0 = blockIdx.x * 32;
    int tx = threadIdx.x, ty = threadIdx.y;
#pragma unroll
    for (int i = 0; i < 4; i++)
        t[ty + i * 8][tx] = w[(long long)(k0 + ty + i * 8) * 4096 + n0 + tx];
    __syncthreads();
#pragma unroll
    for (int i = 0; i < 4; i++) {
        int n = n0 + ty + i * 8, k = k0 + tx;
        o[(long long)n * 4096 + permc(k)] = tf32r(t[tx][ty + i * 8]);
    }
}

// ---------------- host ------------------------------------------------------
extern "C" void kernel_launch(void* const* d_in, const int* in_sizes, int n_in,
                              void* d_out, int out_size) {
    (void)in_sizes; (void)n_in; (void)out_size;
    const float* x    = (const float*)d_in[0];
    const float* abia = (const float*)d_in[1];
    const float* wq   = (const float*)d_in[2];
    const float* bq   = (const float*)d_in[3];
    const float* wk   = (const float*)d_in[4];
    const float* bk   = (const float*)d_in[5];
    const float* wv   = (const float*)d_in[6];
    const float* bv   = (const float*)d_in[7];
    const float* wo   = (const float*)d_in[8];
    const float* bo   = (const float*)d_in[9];
    float* out = (float*)d_out;

    void* p;
    cudaGetSymbolAddress(&p, g_xr);  float* xr  = (float*)p;
    cudaGetSymbolAddress(&p, g_wqr); float* wqr = (float*)p;
    cudaGetSymbolAddress(&p, g_wkr); float* wkr = (float*)p;
    cudaGetSymbolAddress(&p, g_wvr); float* wvr = (float*)p;
    cudaGetSymbolAddress(&p, g_wor); float* wor = (float*)p;
    cudaGetSymbolAddress(&p, g_qr);  float* qr  = (float*)p;
    cudaGetSymbolAddress(&p, g_kr);  float* kr  = (float*)p;
    cudaGetSymbolAddress(&p, g_vt);  float* vt  = (float*)p;
    float* orr = xr;   // xr dead after QKV GEMMs -> reuse for flash output

    cudaFuncSetAttribute(gemm_out_kernel, cudaFuncAttributeMaxDynamicSharedMemorySize, SMEM_GEMM);
    cudaFuncSetAttribute(qkv_kernel,      cudaFuncAttributeMaxDynamicSharedMemorySize, SMEM_GEMM);
    cudaFuncSetAttribute(flash_kernel,    cudaFuncAttributeMaxDynamicSharedMemorySize, SMEM_FLASH);

    rotary_table_kernel<<<(SEQ * 16 + 255) / 256, 256>>>();
    rp_kernel<<<(TOKENS * 1024 + 255) / 256, 256>>>(x, xr, TOKENS * 1024);
    wt_all_kernel<<<dim3(128, 128, 4), dim3(32, 8)>>>(wq, wk, wv, wo, wqr, wkr, wvr, wor);

    // qkv: 8-warp/256-thread (proven); out: 4-warp 64x64 (proven)
    qkv_kernel<<<dim3(1024, 1, 3), 256, SMEM_GEMM>>>(
        xr, wqr, wkr, wvr, qr, kr, vt, bq, bk, bv);

    flash_kernel<<<dim3(8, BATCHN * NHEAD), 256, SMEM_FLASH>>>(qr, kr, vt, abia, orr);

    gemm_out_kernel<<<dim3(1024), 128, SMEM_GEMM>>>(orr, wor, out, bo);
}